// round 2
// baseline (speedup 1.0000x reference)
#include <cuda_runtime.h>

#define NN 1024
#define CD 256
#define HH 4
#define FF 64
#define BROWS 8
#define TMm 32

// scratch (device globals: no allocs allowed)
__device__ float g_gl[NN * CD];
__device__ float g_gr[NN * CD];

// ---------------- GEMM: G = X @ W  (1024x256 @ 256x256) ----------------
__global__ __launch_bounds__(256)
void gemm_kernel(const float* __restrict__ X0, const float* __restrict__ W0,
                 const float* __restrict__ X1, const float* __restrict__ W1) {
    const float* X;
    const float* W;
    float* G;
    if (blockIdx.z == 0) { X = X0; W = W0; G = g_gl; }
    else                 { X = X1; W = W1; G = g_gr; }

    __shared__ float As[16][65];   // [k][row], padded
    __shared__ float Bs[16][64];   // [k][col]

    int t = threadIdx.x;
    int bm = blockIdx.y * 64;
    int bn = blockIdx.x * 64;
    int tr = t >> 4;      // 0..15
    int tc = t & 15;      // 0..15

    float acc[4][4];
#pragma unroll
    for (int i = 0; i < 4; i++)
#pragma unroll
        for (int j = 0; j < 4; j++) acc[i][j] = 0.f;

    for (int k0 = 0; k0 < CD; k0 += 16) {
        {
            int r  = t >> 2;           // 0..63
            int c4 = (t & 3) << 2;     // 0,4,8,12
            float4 av = *(const float4*)(X + (size_t)(bm + r) * CD + k0 + c4);
            As[c4 + 0][r] = av.x; As[c4 + 1][r] = av.y;
            As[c4 + 2][r] = av.z; As[c4 + 3][r] = av.w;
        }
        {
            int r2  = t >> 4;          // 0..15
            int c42 = (t & 15) << 2;   // 0..60
            *(float4*)&Bs[r2][c42] =
                *(const float4*)(W + (size_t)(k0 + r2) * CD + bn + c42);
        }
        __syncthreads();
#pragma unroll
        for (int k = 0; k < 16; k++) {
            float a[4], b[4];
#pragma unroll
            for (int i = 0; i < 4; i++) a[i] = As[k][tr * 4 + i];
#pragma unroll
            for (int j = 0; j < 4; j++) b[j] = Bs[k][tc * 4 + j];
#pragma unroll
            for (int i = 0; i < 4; i++)
#pragma unroll
                for (int j = 0; j < 4; j++) acc[i][j] += a[i] * b[j];
        }
        __syncthreads();
    }
#pragma unroll
    for (int i = 0; i < 4; i++)
#pragma unroll
        for (int j = 0; j < 4; j++)
            G[(size_t)(bm + tr * 4 + i) * CD + bn + tc * 4 + j] = acc[i][j];
}

// ---------------- fused GATv2 attention ----------------
// block = 8 output rows n; loop m in tiles of 32.
// e[n,m,h] = sum_f (0.6*aw[f])*x + (0.4*aw[f])*|x|,  x = g_r[n,h,f] + g_l[m,h,f]
// w = adj[m,n] ? exp(e) : 0 ; out[n,h,f] = (sum_m w * g_r[m,h,f]) / (sum_m w)
__global__ __launch_bounds__(256)
void gat_kernel(const float* __restrict__ adj, const float* __restrict__ attn_w,
                const int* __restrict__ use_elu_p, float* __restrict__ out) {
    __shared__ float sq[BROWS][CD];             // g_r of block rows (queries)
    __shared__ float c1s[FF], c2s[FF];          // 0.6*aw, 0.4*aw
    __shared__ float gl_t[HH][FF][TMm + 1];     // g_l tile transposed [h][f][m]
    __shared__ float w_t[TMm][40];              // [m][h*8 + n], stride 40
    __shared__ float denom_s[BROWS][HH];

    int t  = threadIdx.x;
    int n0 = blockIdx.x * BROWS;

    for (int i = t; i < BROWS * CD; i += 256)
        sq[i >> 8][i & 255] = g_gr[(size_t)(n0 + (i >> 8)) * CD + (i & 255)];
    if (t < FF) {
        float aw = attn_w[t];
        c1s[t] = 0.6f * aw;
        c2s[t] = 0.4f * aw;
    }

    // e-phase mapping: lanes = m, warp-uniform (h, half)
    int em    = t & 31;
    int eq    = t >> 5;        // 0..7
    int eh    = eq & 3;        // head
    int ehalf = eq >> 2;       // 0..1
    int nb    = ehalf * 4;     // n base within block

    // agg mapping: thread = output column c = t, head = c/64
    int ah = t >> 6;

    float dsum[4] = {0.f, 0.f, 0.f, 0.f};
    float acc_out[8];
#pragma unroll
    for (int i = 0; i < 8; i++) acc_out[i] = 0.f;

    for (int tile = 0; tile < NN / TMm; tile++) {
        int m0 = tile * TMm;
        __syncthreads();  // previous agg done before overwriting gl_t / w_t

        // load g_l tile, transposed into [h][f][m] (pad 33 -> conflict-free)
        for (int i = t; i < TMm * CD; i += 256) {
            int m = i >> 8, cc = i & 255;
            gl_t[cc >> 6][cc & 63][m] = g_gl[(size_t)(m0 + m) * CD + cc];
        }
        __syncthreads();

        // ---- e-phase: this thread computes e[n0+nb..nb+3, m0+em, eh] ----
        float aA0 = 0, aA1 = 0, aA2 = 0, aA3 = 0;
        float aB0 = 0, aB1 = 0, aB2 = 0, aB3 = 0;
        const float* sq0 = &sq[nb + 0][eh * FF];
        const float* sq1 = &sq[nb + 1][eh * FF];
        const float* sq2 = &sq[nb + 2][eh * FF];
        const float* sq3 = &sq[nb + 3][eh * FF];
#pragma unroll
        for (int f4 = 0; f4 < FF; f4 += 4) {
            float4 q0 = *(const float4*)(sq0 + f4);
            float4 q1 = *(const float4*)(sq1 + f4);
            float4 q2 = *(const float4*)(sq2 + f4);
            float4 q3 = *(const float4*)(sq3 + f4);
            float4 c1v = *(const float4*)&c1s[f4];
            float4 c2v = *(const float4*)&c2s[f4];
            float g0 = gl_t[eh][f4 + 0][em];
            float g1 = gl_t[eh][f4 + 1][em];
            float g2 = gl_t[eh][f4 + 2][em];
            float g3 = gl_t[eh][f4 + 3][em];
            float x;
            x = q0.x + g0; aA0 += c1v.x * x; aB0 += c2v.x * fabsf(x);
            x = q0.y + g1; aA0 += c1v.y * x; aB0 += c2v.y * fabsf(x);
            x = q0.z + g2; aA0 += c1v.z * x; aB0 += c2v.z * fabsf(x);
            x = q0.w + g3; aA0 += c1v.w * x; aB0 += c2v.w * fabsf(x);
            x = q1.x + g0; aA1 += c1v.x * x; aB1 += c2v.x * fabsf(x);
            x = q1.y + g1; aA1 += c1v.y * x; aB1 += c2v.y * fabsf(x);
            x = q1.z + g2; aA1 += c1v.z * x; aB1 += c2v.z * fabsf(x);
            x = q1.w + g3; aA1 += c1v.w * x; aB1 += c2v.w * fabsf(x);
            x = q2.x + g0; aA2 += c1v.x * x; aB2 += c2v.x * fabsf(x);
            x = q2.y + g1; aA2 += c1v.y * x; aB2 += c2v.y * fabsf(x);
            x = q2.z + g2; aA2 += c1v.z * x; aB2 += c2v.z * fabsf(x);
            x = q2.w + g3; aA2 += c1v.w * x; aB2 += c2v.w * fabsf(x);
            x = q3.x + g0; aA3 += c1v.x * x; aB3 += c2v.x * fabsf(x);
            x = q3.y + g1; aA3 += c1v.y * x; aB3 += c2v.y * fabsf(x);
            x = q3.z + g2; aA3 += c1v.z * x; aB3 += c2v.z * fabsf(x);
            x = q3.w + g3; aA3 += c1v.w * x; aB3 += c2v.w * fabsf(x);
        }
        // mask by adj_mat[m, n] (note: adj.T in the reference), exponentiate
        const float* arow = adj + (size_t)(m0 + em) * NN + n0 + nb;
        float4 am = *(const float4*)arow;
        float e0 = aA0 + aB0, e1 = aA1 + aB1, e2 = aA2 + aB2, e3 = aA3 + aB3;
        float w0 = (am.x != 0.f) ? __expf(e0) : 0.f;
        float w1 = (am.y != 0.f) ? __expf(e1) : 0.f;
        float w2 = (am.z != 0.f) ? __expf(e2) : 0.f;
        float w3 = (am.w != 0.f) ? __expf(e3) : 0.f;
        dsum[0] += w0; dsum[1] += w1; dsum[2] += w2; dsum[3] += w3;
        *(float4*)&w_t[em][eh * 8 + nb] = make_float4(w0, w1, w2, w3);
        __syncthreads();

        // ---- aggregation: acc_out[n] += w[n, m, ah] * g_r[m, c] ----
        const float* grp = g_gr + (size_t)m0 * CD + t;
#pragma unroll 4
        for (int m = 0; m < TMm; m++) {
            float gv  = __ldg(grp + (size_t)m * CD);
            float4 wa = *(const float4*)&w_t[m][ah * 8];
            float4 wb = *(const float4*)&w_t[m][ah * 8 + 4];
            acc_out[0] += wa.x * gv; acc_out[1] += wa.y * gv;
            acc_out[2] += wa.z * gv; acc_out[3] += wa.w * gv;
            acc_out[4] += wb.x * gv; acc_out[5] += wb.y * gv;
            acc_out[6] += wb.z * gv; acc_out[7] += wb.w * gv;
        }
    }

    // reduce dsum over lanes (lanes = m slices) -> denominators
#pragma unroll
    for (int off = 16; off; off >>= 1) {
        dsum[0] += __shfl_xor_sync(0xffffffffu, dsum[0], off);
        dsum[1] += __shfl_xor_sync(0xffffffffu, dsum[1], off);
        dsum[2] += __shfl_xor_sync(0xffffffffu, dsum[2], off);
        dsum[3] += __shfl_xor_sync(0xffffffffu, dsum[3], off);
    }
    if (em == 0) {
        denom_s[nb + 0][eh] = dsum[0];
        denom_s[nb + 1][eh] = dsum[1];
        denom_s[nb + 2][eh] = dsum[2];
        denom_s[nb + 3][eh] = dsum[3];
    }
    __syncthreads();

    int elu = *use_elu_p;  // nonzero-bits check works for int32 or fp32 encodings
#pragma unroll
    for (int n = 0; n < 8; n++) {
        float v = acc_out[n] / denom_s[n][ah];
        if (elu) v = (v > 0.f) ? v : expm1f(v);
        out[(size_t)(n0 + n) * CD + t] = v;
    }
}

extern "C" void kernel_launch(void* const* d_in, const int* in_sizes, int n_in,
                              void* d_out, int out_size) {
    const float* h    = (const float*)d_in[0];
    const float* nei  = (const float*)d_in[1];
    const float* adj  = (const float*)d_in[2];
    const float* w_l  = (const float*)d_in[3];
    const float* w_r  = (const float*)d_in[4];
    const float* aw   = (const float*)d_in[5];
    const int*   uelu = (const int*)d_in[6];
    float* out = (float*)d_out;

    dim3 ggrid(CD / 64, NN / 64, 2);
    gemm_kernel<<<ggrid, 256>>>(h, w_l, nei, w_r);
    gat_kernel<<<NN / BROWS, 256>>>(adj, aw, uelu, out);
}

// round 3
// speedup vs baseline: 1.7889x; 1.7889x over previous
#include <cuda_runtime.h>

#define NN 1024
#define CD 256
#define HH 4
#define FF 64
#define BROWS 8
#define TMm 32
#define NSPLIT 4
#define MPS (NN / NSPLIT)      // m's per split = 256
#define NTILES (MPS / TMm)     // tiles per split = 8

// scratch (device globals: no allocs allowed)
__device__ float g_gl[NN * CD];
__device__ float g_gr[NN * CD];
__device__ float g_pacc[NSPLIT * NN * CD];   // partial numerators
__device__ float g_pden[NSPLIT * NN * HH];   // partial denominators

// ---------------- GEMM: G = X @ W  (1024x256 @ 256x256) ----------------
__global__ __launch_bounds__(256)
void gemm_kernel(const float* __restrict__ X0, const float* __restrict__ W0,
                 const float* __restrict__ X1, const float* __restrict__ W1) {
    const float* X;
    const float* W;
    float* G;
    if (blockIdx.z == 0) { X = X0; W = W0; G = g_gl; }
    else                 { X = X1; W = W1; G = g_gr; }

    __shared__ float As[16][65];   // [k][row], padded
    __shared__ float Bs[16][64];   // [k][col]

    int t = threadIdx.x;
    int bm = blockIdx.y * 64;
    int bn = blockIdx.x * 64;
    int tr = t >> 4;      // 0..15
    int tc = t & 15;      // 0..15

    float acc[4][4];
#pragma unroll
    for (int i = 0; i < 4; i++)
#pragma unroll
        for (int j = 0; j < 4; j++) acc[i][j] = 0.f;

    for (int k0 = 0; k0 < CD; k0 += 16) {
        {
            int r  = t >> 2;           // 0..63
            int c4 = (t & 3) << 2;     // 0,4,8,12
            float4 av = *(const float4*)(X + (size_t)(bm + r) * CD + k0 + c4);
            As[c4 + 0][r] = av.x; As[c4 + 1][r] = av.y;
            As[c4 + 2][r] = av.z; As[c4 + 3][r] = av.w;
        }
        {
            int r2  = t >> 4;          // 0..15
            int c42 = (t & 15) << 2;   // 0..60
            *(float4*)&Bs[r2][c42] =
                *(const float4*)(W + (size_t)(k0 + r2) * CD + bn + c42);
        }
        __syncthreads();
#pragma unroll
        for (int k = 0; k < 16; k++) {
            float a[4], b[4];
#pragma unroll
            for (int i = 0; i < 4; i++) a[i] = As[k][tr * 4 + i];
#pragma unroll
            for (int j = 0; j < 4; j++) b[j] = Bs[k][tc * 4 + j];
#pragma unroll
            for (int i = 0; i < 4; i++)
#pragma unroll
                for (int j = 0; j < 4; j++) acc[i][j] += a[i] * b[j];
        }
        __syncthreads();
    }
#pragma unroll
    for (int i = 0; i < 4; i++)
#pragma unroll
        for (int j = 0; j < 4; j++)
            G[(size_t)(bm + tr * 4 + i) * CD + bn + tc * 4 + j] = acc[i][j];
}

// ---------------- fused GATv2 attention (m-split partials) ----------------
// block = 8 output rows n, 1/NSPLIT of the m range; loop m in tiles of 32.
// e[n,m,h] = sum_f (0.6*aw[f])*x + (0.4*aw[f])*|x|,  x = g_r[n,h,f] + g_l[m,h,f]
// w = adj[m,n] ? exp(e) : 0 ; partial num[n,h,f] = sum_m w*g_r[m,h,f]; den = sum_m w
__global__ __launch_bounds__(256, 4)
void gat_kernel(const float* __restrict__ adj, const float* __restrict__ attn_w) {
    __shared__ float sq[BROWS][CD];             // g_r of block rows (queries)
    __shared__ float c1s[FF], c2s[FF];          // 0.6*aw, 0.4*aw
    __shared__ float gl_t[HH][FF][TMm + 1];     // g_l tile transposed [h][f][m]
    __shared__ float w_t[TMm][40];              // [m][h*8 + n], stride 40

    int t  = threadIdx.x;
    int n0 = blockIdx.x * BROWS;
    int sp = blockIdx.y;
    int mbase = sp * MPS;

    for (int i = t; i < BROWS * CD; i += 256)
        sq[i >> 8][i & 255] = g_gr[(size_t)(n0 + (i >> 8)) * CD + (i & 255)];
    if (t < FF) {
        float aw = attn_w[t];
        c1s[t] = 0.6f * aw;
        c2s[t] = 0.4f * aw;
    }

    // e-phase mapping: lanes = m, warp-uniform (h, half)
    int em    = t & 31;
    int eq    = t >> 5;        // 0..7
    int eh    = eq & 3;        // head
    int ehalf = eq >> 2;       // 0..1
    int nb    = ehalf * 4;     // n base within block

    // agg mapping: thread = output column c = t, head = c/64
    int ah = t >> 6;

    float dsum[4] = {0.f, 0.f, 0.f, 0.f};
    float acc_out[8];
#pragma unroll
    for (int i = 0; i < 8; i++) acc_out[i] = 0.f;

    for (int tile = 0; tile < NTILES; tile++) {
        int m0 = mbase + tile * TMm;
        __syncthreads();  // previous agg done before overwriting gl_t / w_t

        // load g_l tile, transposed into [h][f][m] (pad 33 -> conflict-free)
        for (int i = t; i < TMm * CD; i += 256) {
            int m = i >> 8, cc = i & 255;
            gl_t[cc >> 6][cc & 63][m] = g_gl[(size_t)(m0 + m) * CD + cc];
        }
        __syncthreads();

        // ---- e-phase: this thread computes e[n0+nb..nb+3, m0+em, eh] ----
        float aA0 = 0, aA1 = 0, aA2 = 0, aA3 = 0;
        float aB0 = 0, aB1 = 0, aB2 = 0, aB3 = 0;
        const float* sq0 = &sq[nb + 0][eh * FF];
        const float* sq1 = &sq[nb + 1][eh * FF];
        const float* sq2 = &sq[nb + 2][eh * FF];
        const float* sq3 = &sq[nb + 3][eh * FF];
#pragma unroll
        for (int f4 = 0; f4 < FF; f4 += 4) {
            float4 q0 = *(const float4*)(sq0 + f4);
            float4 q1 = *(const float4*)(sq1 + f4);
            float4 q2 = *(const float4*)(sq2 + f4);
            float4 q3 = *(const float4*)(sq3 + f4);
            float4 c1v = *(const float4*)&c1s[f4];
            float4 c2v = *(const float4*)&c2s[f4];
            float g0 = gl_t[eh][f4 + 0][em];
            float g1 = gl_t[eh][f4 + 1][em];
            float g2 = gl_t[eh][f4 + 2][em];
            float g3 = gl_t[eh][f4 + 3][em];
            float x;
            x = q0.x + g0; aA0 += c1v.x * x; aB0 += c2v.x * fabsf(x);
            x = q0.y + g1; aA0 += c1v.y * x; aB0 += c2v.y * fabsf(x);
            x = q0.z + g2; aA0 += c1v.z * x; aB0 += c2v.z * fabsf(x);
            x = q0.w + g3; aA0 += c1v.w * x; aB0 += c2v.w * fabsf(x);
            x = q1.x + g0; aA1 += c1v.x * x; aB1 += c2v.x * fabsf(x);
            x = q1.y + g1; aA1 += c1v.y * x; aB1 += c2v.y * fabsf(x);
            x = q1.z + g2; aA1 += c1v.z * x; aB1 += c2v.z * fabsf(x);
            x = q1.w + g3; aA1 += c1v.w * x; aB1 += c2v.w * fabsf(x);
            x = q2.x + g0; aA2 += c1v.x * x; aB2 += c2v.x * fabsf(x);
            x = q2.y + g1; aA2 += c1v.y * x; aB2 += c2v.y * fabsf(x);
            x = q2.z + g2; aA2 += c1v.z * x; aB2 += c2v.z * fabsf(x);
            x = q2.w + g3; aA2 += c1v.w * x; aB2 += c2v.w * fabsf(x);
            x = q3.x + g0; aA3 += c1v.x * x; aB3 += c2v.x * fabsf(x);
            x = q3.y + g1; aA3 += c1v.y * x; aB3 += c2v.y * fabsf(x);
            x = q3.z + g2; aA3 += c1v.z * x; aB3 += c2v.z * fabsf(x);
            x = q3.w + g3; aA3 += c1v.w * x; aB3 += c2v.w * fabsf(x);
        }
        // mask by adj_mat[m, n] (note: adj.T in the reference), exponentiate
        const float* arow = adj + (size_t)(m0 + em) * NN + n0 + nb;
        float4 am = *(const float4*)arow;
        float e0 = aA0 + aB0, e1 = aA1 + aB1, e2 = aA2 + aB2, e3 = aA3 + aB3;
        float w0 = (am.x != 0.f) ? __expf(e0) : 0.f;
        float w1 = (am.y != 0.f) ? __expf(e1) : 0.f;
        float w2 = (am.z != 0.f) ? __expf(e2) : 0.f;
        float w3 = (am.w != 0.f) ? __expf(e3) : 0.f;
        dsum[0] += w0; dsum[1] += w1; dsum[2] += w2; dsum[3] += w3;
        *(float4*)&w_t[em][eh * 8 + nb] = make_float4(w0, w1, w2, w3);
        __syncthreads();

        // ---- aggregation: acc_out[n] += w[n, m, ah] * g_r[m, c] ----
        const float* grp = g_gr + (size_t)m0 * CD + t;
#pragma unroll 4
        for (int m = 0; m < TMm; m++) {
            float gv  = __ldg(grp + (size_t)m * CD);
            float4 wa = *(const float4*)&w_t[m][ah * 8];
            float4 wb = *(const float4*)&w_t[m][ah * 8 + 4];
            acc_out[0] += wa.x * gv; acc_out[1] += wa.y * gv;
            acc_out[2] += wa.z * gv; acc_out[3] += wa.w * gv;
            acc_out[4] += wb.x * gv; acc_out[5] += wb.y * gv;
            acc_out[6] += wb.z * gv; acc_out[7] += wb.w * gv;
        }
    }

    // reduce dsum over lanes (lanes = m slices) -> partial denominators
#pragma unroll
    for (int off = 16; off; off >>= 1) {
        dsum[0] += __shfl_xor_sync(0xffffffffu, dsum[0], off);
        dsum[1] += __shfl_xor_sync(0xffffffffu, dsum[1], off);
        dsum[2] += __shfl_xor_sync(0xffffffffu, dsum[2], off);
        dsum[3] += __shfl_xor_sync(0xffffffffu, dsum[3], off);
    }
    if (em == 0) {
#pragma unroll
        for (int i = 0; i < 4; i++)
            g_pden[((size_t)sp * NN + n0 + nb + i) * HH + eh] = dsum[i];
    }

    // partial numerators
#pragma unroll
    for (int n = 0; n < 8; n++)
        g_pacc[((size_t)sp * NN + n0 + n) * CD + t] = acc_out[n];
}

// ---------------- combine partials + elu ----------------
__global__ __launch_bounds__(256)
void combine_kernel(const int* __restrict__ use_elu_p, float* __restrict__ out) {
    int n = blockIdx.x;
    int c = threadIdx.x;
    int h = c >> 6;
    float a = 0.f, d = 0.f;
#pragma unroll
    for (int sp = 0; sp < NSPLIT; sp++) {
        a += g_pacc[((size_t)sp * NN + n) * CD + c];
        d += g_pden[((size_t)sp * NN + n) * HH + h];
    }
    float v = a / d;
    if (*use_elu_p) v = (v > 0.f) ? v : expm1f(v);
    out[(size_t)n * CD + c] = v;
}

extern "C" void kernel_launch(void* const* d_in, const int* in_sizes, int n_in,
                              void* d_out, int out_size) {
    const float* h    = (const float*)d_in[0];
    const float* nei  = (const float*)d_in[1];
    const float* adj  = (const float*)d_in[2];
    const float* w_l  = (const float*)d_in[3];
    const float* w_r  = (const float*)d_in[4];
    const float* aw   = (const float*)d_in[5];
    const int*   uelu = (const int*)d_in[6];
    float* out = (float*)d_out;

    dim3 ggrid(CD / 64, NN / 64, 2);
    gemm_kernel<<<ggrid, 256>>>(h, w_l, nei, w_r);
    dim3 agrid(NN / BROWS, NSPLIT);
    gat_kernel<<<agrid, 256>>>(adj, aw);
    combine_kernel<<<NN, 256>>>(uelu, out);
}

// round 4
// speedup vs baseline: 1.9211x; 1.0739x over previous
#include <cuda_runtime.h>

#define NN 1024
#define CD 256
#define HH 4
#define FF 64
#define BROWS 8
#define TMm 32
#define NSPLIT 4
#define MPS (NN / NSPLIT)      // m's per split = 256
#define NTILES (MPS / TMm)     // tiles per split = 8

typedef unsigned long long ull;
#define ABSM 0x7FFFFFFF7FFFFFFFULL

__device__ __forceinline__ ull fma2(ull a, ull b, ull c) {
    ull d;
    asm("fma.rn.f32x2 %0, %1, %2, %3;" : "=l"(d) : "l"(a), "l"(b), "l"(c));
    return d;
}
__device__ __forceinline__ ull add2(ull a, ull b) {
    ull d;
    asm("add.rn.f32x2 %0, %1, %2;" : "=l"(d) : "l"(a), "l"(b));
    return d;
}
__device__ __forceinline__ ull pack2(float lo, float hi) {
    ull d;
    asm("mov.b64 %0, {%1, %2};" : "=l"(d) : "f"(lo), "f"(hi));
    return d;
}
__device__ __forceinline__ float2 unpack2(ull v) {
    float2 r;
    asm("mov.b64 {%0, %1}, %2;" : "=f"(r.x), "=f"(r.y) : "l"(v));
    return r;
}

// scratch (device globals: no allocs allowed)
__device__ float g_gl[NN * CD];
__device__ float g_gr[NN * CD];
__device__ float g_pacc[NSPLIT * NN * CD];   // partial numerators
__device__ float g_pden[NSPLIT * NN * HH];   // partial denominators

// ---------------- GEMM: G = X @ W  (1024x256 @ 256x256), 32x64 tiles ----------------
__global__ __launch_bounds__(256)
void gemm_kernel(const float* __restrict__ X0, const float* __restrict__ W0,
                 const float* __restrict__ X1, const float* __restrict__ W1) {
    const float* X;
    const float* W;
    float* G;
    if (blockIdx.z == 0) { X = X0; W = W0; G = g_gl; }
    else                 { X = X1; W = W1; G = g_gr; }

    __shared__ __align__(16) float As[16][34];   // [k][row], even pad -> 8B-aligned pairs
    __shared__ __align__(16) float Bs[16][64];   // [k][col]

    int t = threadIdx.x;
    int bm = blockIdx.y * 32;
    int bn = blockIdx.x * 64;
    int tr = t >> 4;      // 0..15 -> 2 rows each
    int tc = t & 15;      // 0..15 -> 4 cols each

    ull acc00 = 0, acc01 = 0, acc10 = 0, acc11 = 0;

    for (int k0 = 0; k0 < CD; k0 += 16) {
        if (t < 128) {
            int r  = t >> 2;           // 0..31
            int c4 = (t & 3) << 2;     // 0,4,8,12
            float4 av = *(const float4*)(X + (size_t)(bm + r) * CD + k0 + c4);
            As[c4 + 0][r] = av.x; As[c4 + 1][r] = av.y;
            As[c4 + 2][r] = av.z; As[c4 + 3][r] = av.w;
        }
        {
            int r2  = t >> 4;          // 0..15
            int c42 = (t & 15) << 2;   // 0..60
            *(float4*)&Bs[r2][c42] =
                *(const float4*)(W + (size_t)(k0 + r2) * CD + bn + c42);
        }
        __syncthreads();
#pragma unroll
        for (int k = 0; k < 16; k++) {
            float2 a = *(const float2*)&As[k][tr * 2];
            ulonglong2 b = *(const ulonglong2*)&Bs[k][tc * 4];
            ull a0 = pack2(a.x, a.x);
            ull a1 = pack2(a.y, a.y);
            acc00 = fma2(a0, b.x, acc00);
            acc01 = fma2(a0, b.y, acc01);
            acc10 = fma2(a1, b.x, acc10);
            acc11 = fma2(a1, b.y, acc11);
        }
        __syncthreads();
    }
    {
        float2 p0 = unpack2(acc00), p1 = unpack2(acc01);
        *(float4*)&G[(size_t)(bm + tr * 2 + 0) * CD + bn + tc * 4] =
            make_float4(p0.x, p0.y, p1.x, p1.y);
        float2 q0 = unpack2(acc10), q1 = unpack2(acc11);
        *(float4*)&G[(size_t)(bm + tr * 2 + 1) * CD + bn + tc * 4] =
            make_float4(q0.x, q0.y, q1.x, q1.y);
    }
}

// ---------------- fused GATv2 attention (m-split partials, f32x2) ----------------
__global__ __launch_bounds__(256, 4)
void gat_kernel(const float* __restrict__ adj, const float* __restrict__ attn_w) {
    __shared__ __align__(16) float sq[BROWS][CD];       // g_r of block rows (queries)
    __shared__ __align__(16) float c1s[FF], c2s[FF];    // 0.6*aw, 0.4*aw
    __shared__ ull gl_p[HH][FF / 2][TMm + 1];           // g_l tile, f-pairs packed
    __shared__ __align__(16) float w_t[TMm][40];        // [m][h*8 + n], stride 40

    int t  = threadIdx.x;
    int n0 = blockIdx.x * BROWS;
    int sp = blockIdx.y;
    int mbase = sp * MPS;

    for (int i = t; i < BROWS * CD; i += 256)
        sq[i >> 8][i & 255] = g_gr[(size_t)(n0 + (i >> 8)) * CD + (i & 255)];
    if (t < FF) {
        float aw = attn_w[t];
        c1s[t] = 0.6f * aw;
        c2s[t] = 0.4f * aw;
    }

    // e-phase mapping: lanes = m, warp-uniform (h, half)
    int em    = t & 31;
    int eq    = t >> 5;        // 0..7
    int eh    = eq & 3;        // head
    int ehalf = eq >> 2;       // 0..1
    int nb    = ehalf * 4;     // n base within block

    // agg mapping: thread = output column c = t, head = c/64
    int ah = t >> 6;

    float dsum[4] = {0.f, 0.f, 0.f, 0.f};
    ull accp[4] = {0ULL, 0ULL, 0ULL, 0ULL};   // n-pairs (01,23,45,67)

    const ull* q0 = (const ull*)&sq[nb + 0][eh * FF];
    const ull* q1 = (const ull*)&sq[nb + 1][eh * FF];
    const ull* q2 = (const ull*)&sq[nb + 2][eh * FF];
    const ull* q3 = (const ull*)&sq[nb + 3][eh * FF];
    const ull* c1p = (const ull*)c1s;
    const ull* c2p = (const ull*)c2s;

    for (int tile = 0; tile < NTILES; tile++) {
        int m0 = mbase + tile * TMm;
        __syncthreads();  // previous agg done before overwriting gl_p / w_t

        // load g_l tile as packed f-pairs: gl_p[h][fp][m]
        // lanes: consecutive cc, same m -> coalesced 8B global reads;
        // smem write stride 33 ull -> conflict-free (64-bit, 16-lane phases)
        for (int i = t; i < TMm * (CD / 2); i += 256) {
            int m  = i >> 7;        // 0..31
            int cc = i & 127;       // global f-pair (h*32 + fp)
            ull v = *(const ull*)(g_gl + (size_t)(m0 + m) * CD + 2 * cc);
            gl_p[cc >> 5][cc & 31][m] = v;
        }
        __syncthreads();

        // ---- e-phase: e[n0+nb..nb+3, m0+em, eh], packed over f-pairs ----
        ull aA0 = 0, aA1 = 0, aA2 = 0, aA3 = 0;
        ull aB0 = 0, aB1 = 0, aB2 = 0, aB3 = 0;
        const ull* gp = &gl_p[eh][0][em];
#pragma unroll
        for (int fp = 0; fp < FF / 2; fp++) {
            ull c1 = c1p[fp];
            ull c2 = c2p[fp];
            ull g  = gp[fp * (TMm + 1)];
            ull x;
            x = add2(q0[fp], g); aA0 = fma2(c1, x, aA0); aB0 = fma2(c2, x & ABSM, aB0);
            x = add2(q1[fp], g); aA1 = fma2(c1, x, aA1); aB1 = fma2(c2, x & ABSM, aB1);
            x = add2(q2[fp], g); aA2 = fma2(c1, x, aA2); aB2 = fma2(c2, x & ABSM, aB2);
            x = add2(q3[fp], g); aA3 = fma2(c1, x, aA3); aB3 = fma2(c2, x & ABSM, aB3);
        }
        float2 s0 = unpack2(add2(aA0, aB0));
        float2 s1 = unpack2(add2(aA1, aB1));
        float2 s2 = unpack2(add2(aA2, aB2));
        float2 s3 = unpack2(add2(aA3, aB3));
        float e0 = s0.x + s0.y, e1 = s1.x + s1.y;
        float e2 = s2.x + s2.y, e3 = s3.x + s3.y;

        // mask by adj_mat[m, n] (adj.T in the reference), exponentiate
        const float* arow = adj + (size_t)(m0 + em) * NN + n0 + nb;
        float4 am = *(const float4*)arow;
        float w0 = (am.x != 0.f) ? __expf(e0) : 0.f;
        float w1 = (am.y != 0.f) ? __expf(e1) : 0.f;
        float w2 = (am.z != 0.f) ? __expf(e2) : 0.f;
        float w3 = (am.w != 0.f) ? __expf(e3) : 0.f;
        dsum[0] += w0; dsum[1] += w1; dsum[2] += w2; dsum[3] += w3;
        *(float4*)&w_t[em][eh * 8 + nb] = make_float4(w0, w1, w2, w3);
        __syncthreads();

        // ---- aggregation: accp[np] += w[n-pair, m, ah] * (gv, gv) ----
        const float* grp = g_gr + (size_t)m0 * CD + t;
#pragma unroll 4
        for (int m = 0; m < TMm; m++) {
            float gv = __ldg(grp + (size_t)m * CD);
            ull gv2 = pack2(gv, gv);
            ulonglong2 wa = *(const ulonglong2*)&w_t[m][ah * 8];
            ulonglong2 wb = *(const ulonglong2*)&w_t[m][ah * 8 + 4];
            accp[0] = fma2(wa.x, gv2, accp[0]);
            accp[1] = fma2(wa.y, gv2, accp[1]);
            accp[2] = fma2(wb.x, gv2, accp[2]);
            accp[3] = fma2(wb.y, gv2, accp[3]);
        }
    }

    // reduce dsum over lanes (lanes = m slices) -> partial denominators
#pragma unroll
    for (int off = 16; off; off >>= 1) {
        dsum[0] += __shfl_xor_sync(0xffffffffu, dsum[0], off);
        dsum[1] += __shfl_xor_sync(0xffffffffu, dsum[1], off);
        dsum[2] += __shfl_xor_sync(0xffffffffu, dsum[2], off);
        dsum[3] += __shfl_xor_sync(0xffffffffu, dsum[3], off);
    }
    if (em == 0) {
#pragma unroll
        for (int i = 0; i < 4; i++)
            g_pden[((size_t)sp * NN + n0 + nb + i) * HH + eh] = dsum[i];
    }

    // partial numerators
#pragma unroll
    for (int np = 0; np < 4; np++) {
        float2 v = unpack2(accp[np]);
        g_pacc[((size_t)sp * NN + n0 + 2 * np + 0) * CD + t] = v.x;
        g_pacc[((size_t)sp * NN + n0 + 2 * np + 1) * CD + t] = v.y;
    }
}

// ---------------- combine partials + elu ----------------
__global__ __launch_bounds__(256)
void combine_kernel(const int* __restrict__ use_elu_p, float* __restrict__ out) {
    int n = blockIdx.x;
    int c = threadIdx.x;
    int h = c >> 6;
    float a = 0.f, d = 0.f;
#pragma unroll
    for (int sp = 0; sp < NSPLIT; sp++) {
        a += g_pacc[((size_t)sp * NN + n) * CD + c];
        d += g_pden[((size_t)sp * NN + n) * HH + h];
    }
    float v = a / d;
    if (*use_elu_p) v = (v > 0.f) ? v : expm1f(v);
    out[(size_t)n * CD + c] = v;
}

extern "C" void kernel_launch(void* const* d_in, const int* in_sizes, int n_in,
                              void* d_out, int out_size) {
    const float* h    = (const float*)d_in[0];
    const float* nei  = (const float*)d_in[1];
    const float* adj  = (const float*)d_in[2];
    const float* w_l  = (const float*)d_in[3];
    const float* w_r  = (const float*)d_in[4];
    const float* aw   = (const float*)d_in[5];
    const int*   uelu = (const int*)d_in[6];
    float* out = (float*)d_out;

    dim3 ggrid(CD / 64, NN / 32, 2);
    gemm_kernel<<<ggrid, 256>>>(h, w_l, nei, w_r);
    dim3 agrid(NN / BROWS, NSPLIT);
    gat_kernel<<<agrid, 256>>>(adj, aw);
    combine_kernel<<<NN, 256>>>(uelu, out);
}

// round 5
// speedup vs baseline: 1.9663x; 1.0236x over previous
#include <cuda_runtime.h>

#define NN 1024
#define CD 256
#define HH 4
#define FF 64
#define BROWS 8
#define TMm 32
#define NSPLIT 4
#define MPS (NN / NSPLIT)      // m's per split = 256
#define NTILES (MPS / TMm)     // tiles per split = 8
#define WTS 36                 // w_t row stride (floats): 144B -> conflict-free STS.128

typedef unsigned long long ull;
#define ABSM 0x7FFFFFFF7FFFFFFFULL

__device__ __forceinline__ ull fma2(ull a, ull b, ull c) {
    ull d;
    asm("fma.rn.f32x2 %0, %1, %2, %3;" : "=l"(d) : "l"(a), "l"(b), "l"(c));
    return d;
}
__device__ __forceinline__ ull add2(ull a, ull b) {
    ull d;
    asm("add.rn.f32x2 %0, %1, %2;" : "=l"(d) : "l"(a), "l"(b));
    return d;
}
__device__ __forceinline__ ull pack2(float lo, float hi) {
    ull d;
    asm("mov.b64 %0, {%1, %2};" : "=l"(d) : "f"(lo), "f"(hi));
    return d;
}
__device__ __forceinline__ float2 unpack2(ull v) {
    float2 r;
    asm("mov.b64 {%0, %1}, %2;" : "=f"(r.x), "=f"(r.y) : "l"(v));
    return r;
}
__device__ __forceinline__ float hsum2(ull v) {
    float2 r = unpack2(v);
    return r.x + r.y;
}

// scratch (device globals: no allocs allowed)
__device__ float g_gl[NN * CD];
__device__ float g_gr[NN * CD];
__device__ float g_pacc[NSPLIT * NN * CD];   // partial numerators
__device__ float g_pden[NSPLIT * NN * HH];   // partial denominators

// ---------------- GEMM: G = X @ W  (1024x256 @ 256x256), 32x64 tiles ----------------
__global__ __launch_bounds__(256)
void gemm_kernel(const float* __restrict__ X0, const float* __restrict__ W0,
                 const float* __restrict__ X1, const float* __restrict__ W1) {
    const float* X;
    const float* W;
    float* G;
    if (blockIdx.z == 0) { X = X0; W = W0; G = g_gl; }
    else                 { X = X1; W = W1; G = g_gr; }

    __shared__ __align__(16) ull   As[16][34];   // [k][row] value duplicated (a,a); 272B rows, 16B-aligned
    __shared__ __align__(16) float Bs[16][64];   // [k][col]

    int t = threadIdx.x;
    int bm = blockIdx.y * 32;
    int bn = blockIdx.x * 64;
    int tr = t >> 4;      // 0..15 -> rows tr*2, tr*2+1
    int tc = t & 15;      // 0..15 -> cols tc*4

    ull acc00 = 0, acc01 = 0, acc10 = 0, acc11 = 0;

    for (int k0 = 0; k0 < CD; k0 += 16) {
        if (t < 128) {
            int r  = t >> 2;           // 0..31
            int c4 = (t & 3) << 2;     // 0,4,8,12
            float4 av = *(const float4*)(X + (size_t)(bm + r) * CD + k0 + c4);
            As[c4 + 0][r] = pack2(av.x, av.x);
            As[c4 + 1][r] = pack2(av.y, av.y);
            As[c4 + 2][r] = pack2(av.z, av.z);
            As[c4 + 3][r] = pack2(av.w, av.w);
        }
        {
            int r2  = t >> 4;          // 0..15
            int c42 = (t & 15) << 2;   // 0..60
            *(float4*)&Bs[r2][c42] =
                *(const float4*)(W + (size_t)(k0 + r2) * CD + bn + c42);
        }
        __syncthreads();
#pragma unroll
        for (int k = 0; k < 16; k++) {
            ulonglong2 a2 = *(const ulonglong2*)&As[k][tr * 2];
            ulonglong2 b2 = *(const ulonglong2*)&Bs[k][tc * 4];
            acc00 = fma2(a2.x, b2.x, acc00);
            acc01 = fma2(a2.x, b2.y, acc01);
            acc10 = fma2(a2.y, b2.x, acc10);
            acc11 = fma2(a2.y, b2.y, acc11);
        }
        __syncthreads();
    }
    {
        float2 p0 = unpack2(acc00), p1 = unpack2(acc01);
        *(float4*)&G[(size_t)(bm + tr * 2 + 0) * CD + bn + tc * 4] =
            make_float4(p0.x, p0.y, p1.x, p1.y);
        float2 q0 = unpack2(acc10), q1 = unpack2(acc11);
        *(float4*)&G[(size_t)(bm + tr * 2 + 1) * CD + bn + tc * 4] =
            make_float4(q0.x, q0.y, q1.x, q1.y);
    }
}

// ---------------- fused GATv2 attention (m-split partials, f32x2) ----------------
// e[n,m,h] = ecq[n,h] + ecg[m,h] + sum_f c2[f]*|q+g|
//   ecq[n,h] = sum_f c1[f]*q[n,h,f]   (precomputed per block)
//   ecg[m,h] = sum_f c1[f]*g[m,h,f]   (accumulated in inner loop, n-independent)
__global__ __launch_bounds__(256, 4)
void gat_kernel(const float* __restrict__ adj, const float* __restrict__ attn_w) {
    __shared__ __align__(16) float sq[BROWS][CD];        // g_r of block rows (queries)
    __shared__ __align__(16) float c1s[FF], c2s[FF];     // 0.6*aw, 0.4*aw
    __shared__ ulonglong2 gl2[HH][FF / 4][TMm + 1];      // g_l tile, 4-f groups [h][fp2][m]
    __shared__ __align__(16) float w_t[TMm][WTS];        // [m][h*8 + n]
    __shared__ float ecq_s[BROWS][HH];

    int t  = threadIdx.x;
    int n0 = blockIdx.x * BROWS;
    int sp = blockIdx.y;
    int mbase = sp * MPS;

    // load queries (as 16B) + coefficient vectors
    {
        ulonglong2* sq2 = (ulonglong2*)sq;
        for (int i = t; i < BROWS * CD / 4; i += 256) {
            int r = i >> 6, c2 = i & 63;
            sq2[i] = *(const ulonglong2*)(g_gr + (size_t)(n0 + r) * CD + 4 * c2);
        }
    }
    if (t < FF) {
        float aw = attn_w[t];
        c1s[t] = 0.6f * aw;
        c2s[t] = 0.4f * aw;
    }
    __syncthreads();

    // precompute ecq[n][h] = sum_f c1[f] * q[n,h,f]
    if (t < BROWS * HH) {
        int n = t >> 2, h = t & 3;
        const ull* qp = (const ull*)&sq[n][h * FF];
        const ull* cp = (const ull*)c1s;
        ull s = 0;
#pragma unroll
        for (int i = 0; i < FF / 2; i++) s = fma2(cp[i], qp[i], s);
        ecq_s[n][h] = hsum2(s);
    }

    // e-phase threads: t < 128 -> em = lane (m within tile), eh = warp
    int em = t & 31;
    int eh = t >> 5;           // 0..3 valid when t < 128
    bool ethr = t < 128;

    // agg mapping: thread = output column c = t, head = c/64
    int ah = t >> 6;

    float dsum[BROWS];
#pragma unroll
    for (int i = 0; i < BROWS; i++) dsum[i] = 0.f;
    ull accp[4] = {0ULL, 0ULL, 0ULL, 0ULL};   // n-pairs (01,23,45,67)

    for (int tile = 0; tile < NTILES; tile++) {
        int m0 = mbase + tile * TMm;
        __syncthreads();  // previous agg done before overwriting gl2 / w_t

        // load g_l tile as 16B groups: gl2[h][fp2][m]
        {
            for (int i = t; i < TMm * (CD / 4); i += 256) {
                int m   = i >> 6;        // 0..31
                int cc2 = i & 63;        // global 4-f group (h*16 + fp2)
                ulonglong2 v = *(const ulonglong2*)(g_gl + (size_t)(m0 + m) * CD + 4 * cc2);
                gl2[cc2 >> 4][cc2 & 15][m] = v;
            }
        }
        __syncthreads();

        if (ethr) {
            // ---- e-phase: e[n0..n0+7, m0+em, eh] ----
            ull aB0 = 0, aB1 = 0, aB2 = 0, aB3 = 0;
            ull aB4 = 0, aB5 = 0, aB6 = 0, aB7 = 0;
            ull ecg = 0;
            const ulonglong2* gp  = &gl2[eh][0][em];
            const ulonglong2* qb  = (const ulonglong2*)&sq[0][eh * FF];  // n stride = 64 ulonglong2
            const ulonglong2* c1p = (const ulonglong2*)c1s;
            const ulonglong2* c2p = (const ulonglong2*)c2s;
#pragma unroll
            for (int fp2 = 0; fp2 < FF / 4; fp2++) {
                ulonglong2 c1v = c1p[fp2];
                ulonglong2 c2v = c2p[fp2];
                ulonglong2 g   = gp[fp2 * (TMm + 1)];
                ecg = fma2(c1v.x, g.x, ecg);
                ecg = fma2(c1v.y, g.y, ecg);
                ull x0, x1;
                ulonglong2 qv;
#define EABS(N, ACC) \
                qv = qb[(N) * 64 + fp2]; \
                x0 = add2(qv.x, g.x); x1 = add2(qv.y, g.y); \
                ACC = fma2(c2v.x, x0 & ABSM, ACC); \
                ACC = fma2(c2v.y, x1 & ABSM, ACC);
                EABS(0, aB0) EABS(1, aB1) EABS(2, aB2) EABS(3, aB3)
                EABS(4, aB4) EABS(5, aB5) EABS(6, aB6) EABS(7, aB7)
#undef EABS
            }
            float ecgs = hsum2(ecg);

            // mask by adj_mat[m, n] (adj.T in the reference), exponentiate
            const float* arow = adj + (size_t)(m0 + em) * NN + n0;
            float4 am0 = *(const float4*)arow;
            float4 am1 = *(const float4*)(arow + 4);
            float w0 = (am0.x != 0.f) ? __expf(hsum2(aB0) + ecgs + ecq_s[0][eh]) : 0.f;
            float w1 = (am0.y != 0.f) ? __expf(hsum2(aB1) + ecgs + ecq_s[1][eh]) : 0.f;
            float w2 = (am0.z != 0.f) ? __expf(hsum2(aB2) + ecgs + ecq_s[2][eh]) : 0.f;
            float w3 = (am0.w != 0.f) ? __expf(hsum2(aB3) + ecgs + ecq_s[3][eh]) : 0.f;
            float w4 = (am1.x != 0.f) ? __expf(hsum2(aB4) + ecgs + ecq_s[4][eh]) : 0.f;
            float w5 = (am1.y != 0.f) ? __expf(hsum2(aB5) + ecgs + ecq_s[5][eh]) : 0.f;
            float w6 = (am1.z != 0.f) ? __expf(hsum2(aB6) + ecgs + ecq_s[6][eh]) : 0.f;
            float w7 = (am1.w != 0.f) ? __expf(hsum2(aB7) + ecgs + ecq_s[7][eh]) : 0.f;
            dsum[0] += w0; dsum[1] += w1; dsum[2] += w2; dsum[3] += w3;
            dsum[4] += w4; dsum[5] += w5; dsum[6] += w6; dsum[7] += w7;
            *(float4*)&w_t[em][eh * 8 + 0] = make_float4(w0, w1, w2, w3);
            *(float4*)&w_t[em][eh * 8 + 4] = make_float4(w4, w5, w6, w7);
        }
        __syncthreads();

        // ---- aggregation: accp[np] += w[n-pair, m, ah] * (gv, gv) ----
        const float* grp = g_gr + (size_t)m0 * CD + t;
#pragma unroll 4
        for (int m = 0; m < TMm; m++) {
            float gv = __ldg(grp + (size_t)m * CD);
            ull gv2 = pack2(gv, gv);
            ulonglong2 wa = *(const ulonglong2*)&w_t[m][ah * 8];
            ulonglong2 wb = *(const ulonglong2*)&w_t[m][ah * 8 + 4];
            accp[0] = fma2(wa.x, gv2, accp[0]);
            accp[1] = fma2(wa.y, gv2, accp[1]);
            accp[2] = fma2(wb.x, gv2, accp[2]);
            accp[3] = fma2(wb.y, gv2, accp[3]);
        }
    }

    // reduce dsum over lanes (lanes = m slices) -> partial denominators
    if (ethr) {
#pragma unroll
        for (int off = 16; off; off >>= 1) {
#pragma unroll
            for (int i = 0; i < BROWS; i++)
                dsum[i] += __shfl_xor_sync(0xffffffffu, dsum[i], off);
        }
        if (em == 0) {
#pragma unroll
            for (int i = 0; i < BROWS; i++)
                g_pden[((size_t)sp * NN + n0 + i) * HH + eh] = dsum[i];
        }
    }

    // partial numerators
#pragma unroll
    for (int np = 0; np < 4; np++) {
        float2 v = unpack2(accp[np]);
        g_pacc[((size_t)sp * NN + n0 + 2 * np + 0) * CD + t] = v.x;
        g_pacc[((size_t)sp * NN + n0 + 2 * np + 1) * CD + t] = v.y;
    }
}

// ---------------- combine partials + elu ----------------
__global__ __launch_bounds__(256)
void combine_kernel(const int* __restrict__ use_elu_p, float* __restrict__ out) {
    int n = blockIdx.x;
    int c = threadIdx.x;
    int h = c >> 6;
    float a = 0.f, d = 0.f;
#pragma unroll
    for (int sp = 0; sp < NSPLIT; sp++) {
        a += g_pacc[((size_t)sp * NN + n) * CD + c];
        d += g_pden[((size_t)sp * NN + n) * HH + h];
    }
    float v = a / d;
    if (*use_elu_p) v = (v > 0.f) ? v : expm1f(v);
    out[(size_t)n * CD + c] = v;
}

extern "C" void kernel_launch(void* const* d_in, const int* in_sizes, int n_in,
                              void* d_out, int out_size) {
    const float* h    = (const float*)d_in[0];
    const float* nei  = (const float*)d_in[1];
    const float* adj  = (const float*)d_in[2];
    const float* w_l  = (const float*)d_in[3];
    const float* w_r  = (const float*)d_in[4];
    const float* aw   = (const float*)d_in[5];
    const int*   uelu = (const int*)d_in[6];
    float* out = (float*)d_out;

    dim3 ggrid(CD / 64, NN / 32, 2);
    gemm_kernel<<<ggrid, 256>>>(h, w_l, nei, w_r);
    dim3 agrid(NN / BROWS, NSPLIT);
    gat_kernel<<<agrid, 256>>>(adj, aw);
    combine_kernel<<<NN, 256>>>(uelu, out);
}

// round 6
// speedup vs baseline: 2.0803x; 1.0580x over previous
#include <cuda_runtime.h>

#define NN 1024
#define CD 256
#define HH 4
#define FF 64
#define BROWS 8
#define TMm 32
#define NSPLIT 4
#define MPS (NN / NSPLIT)      // m's per split = 256
#define NTILES (MPS / TMm)     // tiles per split = 8
#define WTS 36                 // w_t row stride (floats): 144B -> conflict-free STS.128

typedef unsigned long long ull;
#define ABSM 0x7FFFFFFF7FFFFFFFULL

__device__ __forceinline__ ull fma2(ull a, ull b, ull c) {
    ull d;
    asm("fma.rn.f32x2 %0, %1, %2, %3;" : "=l"(d) : "l"(a), "l"(b), "l"(c));
    return d;
}
__device__ __forceinline__ ull add2(ull a, ull b) {
    ull d;
    asm("add.rn.f32x2 %0, %1, %2;" : "=l"(d) : "l"(a), "l"(b));
    return d;
}
__device__ __forceinline__ ull pack2(float lo, float hi) {
    ull d;
    asm("mov.b64 %0, {%1, %2};" : "=l"(d) : "f"(lo), "f"(hi));
    return d;
}
__device__ __forceinline__ float2 unpack2(ull v) {
    float2 r;
    asm("mov.b64 {%0, %1}, %2;" : "=f"(r.x), "=f"(r.y) : "l"(v));
    return r;
}
__device__ __forceinline__ float hsum2(ull v) {
    float2 r = unpack2(v);
    return r.x + r.y;
}

// scratch (device globals: no allocs allowed)
__device__ float g_gl[NN * CD];
__device__ float g_gr[NN * CD];
__device__ float g_pacc[NSPLIT * NN * CD];   // partial numerators
__device__ float g_pden[NSPLIT * NN * HH];   // partial denominators

// ------- GEMM: G = X @ W  (1024x256 @ 256x256), 32x64 tiles, double-buffered -------
__global__ __launch_bounds__(256)
void gemm_kernel(const float* __restrict__ X0, const float* __restrict__ W0,
                 const float* __restrict__ X1, const float* __restrict__ W1) {
    const float* X;
    const float* W;
    float* G;
    if (blockIdx.z == 0) { X = X0; W = W0; G = g_gl; }
    else                 { X = X1; W = W1; G = g_gr; }

    __shared__ __align__(16) float As[2][16][34];   // [buf][k][row]
    __shared__ __align__(16) float Bs[2][16][64];   // [buf][k][col]

    int t = threadIdx.x;
    int bm = blockIdx.y * 32;
    int bn = blockIdx.x * 64;
    int tr = t >> 4;      // 0..15 -> rows tr*2, tr*2+1
    int tc = t & 15;      // 0..15 -> cols tc*4

    // loader indices
    int ar  = t >> 2;            // 0..63 (use <32)
    int ac4 = (t & 3) << 2;      // 0,4,8,12
    int br  = t >> 4;            // 0..15
    int bc4 = (t & 15) << 2;     // 0..60

    ull acc00 = 0, acc01 = 0, acc10 = 0, acc11 = 0;

    float4 av, bv;
    if (t < 128)
        av = *(const float4*)(X + (size_t)(bm + ar) * CD + ac4);
    bv = *(const float4*)(W + (size_t)br * CD + bn + bc4);
    if (t < 128) {
        As[0][ac4 + 0][ar] = av.x; As[0][ac4 + 1][ar] = av.y;
        As[0][ac4 + 2][ar] = av.z; As[0][ac4 + 3][ar] = av.w;
    }
    *(float4*)&Bs[0][br][bc4] = bv;
    __syncthreads();

    for (int kc = 0; kc < 16; kc++) {
        int cur = kc & 1;
        if (kc < 15) {
            if (t < 128)
                av = *(const float4*)(X + (size_t)(bm + ar) * CD + (kc + 1) * 16 + ac4);
            bv = *(const float4*)(W + (size_t)((kc + 1) * 16 + br) * CD + bn + bc4);
        }
#pragma unroll
        for (int k = 0; k < 16; k++) {
            float2 a = *(const float2*)&As[cur][k][tr * 2];
            ulonglong2 b2 = *(const ulonglong2*)&Bs[cur][k][tc * 4];
            ull a0 = pack2(a.x, a.x);
            ull a1 = pack2(a.y, a.y);
            acc00 = fma2(a0, b2.x, acc00);
            acc01 = fma2(a0, b2.y, acc01);
            acc10 = fma2(a1, b2.x, acc10);
            acc11 = fma2(a1, b2.y, acc11);
        }
        if (kc < 15) {
            int nxt = cur ^ 1;
            if (t < 128) {
                As[nxt][ac4 + 0][ar] = av.x; As[nxt][ac4 + 1][ar] = av.y;
                As[nxt][ac4 + 2][ar] = av.z; As[nxt][ac4 + 3][ar] = av.w;
            }
            *(float4*)&Bs[nxt][br][bc4] = bv;
        }
        __syncthreads();
    }
    {
        float2 p0 = unpack2(acc00), p1 = unpack2(acc01);
        *(float4*)&G[(size_t)(bm + tr * 2 + 0) * CD + bn + tc * 4] =
            make_float4(p0.x, p0.y, p1.x, p1.y);
        float2 q0 = unpack2(acc10), q1 = unpack2(acc11);
        *(float4*)&G[(size_t)(bm + tr * 2 + 1) * CD + bn + tc * 4] =
            make_float4(q0.x, q0.y, q1.x, q1.y);
    }
}

// ---------------- fused GATv2 attention (m-split partials, f32x2) ----------------
// e[n,m,h] = ecq[n,h] + ecg[m,h] + sum_f c2[f]*|q+g|
//   ecq[n,h] = sum_f c1[f]*q[n,h,f]   (precomputed per block)
//   ecg[m,h] = sum_f c1[f]*g[m,h,f]   (accumulated in inner loop, n-independent)
// e-phase threads: all 256. thread = (em=lane, eh=warp&3, half=warp>>2), 4 n's each.
__global__ __launch_bounds__(256, 4)
void gat_kernel(const float* __restrict__ adj, const float* __restrict__ attn_w) {
    __shared__ __align__(16) float sq[BROWS][CD];        // g_r of block rows (queries)
    __shared__ __align__(16) float c1s[FF], c2s[FF];     // 0.6*aw, 0.4*aw
    __shared__ ulonglong2 gl2[HH][FF / 4][TMm + 1];      // g_l tile, 4-f groups [h][fp2][m]
    __shared__ __align__(16) float w_t[TMm][WTS];        // [m][h*8 + n]
    __shared__ float ecq_s[BROWS][HH];

    int t  = threadIdx.x;
    int n0 = blockIdx.x * BROWS;
    int sp = blockIdx.y;
    int mbase = sp * MPS;

    // load queries (as 16B) + coefficient vectors
    {
        ulonglong2* sq2 = (ulonglong2*)sq;
        for (int i = t; i < BROWS * CD / 4; i += 256) {
            int r = i >> 6, c2 = i & 63;
            sq2[i] = *(const ulonglong2*)(g_gr + (size_t)(n0 + r) * CD + 4 * c2);
        }
    }
    if (t < FF) {
        float aw = attn_w[t];
        c1s[t] = 0.6f * aw;
        c2s[t] = 0.4f * aw;
    }
    __syncthreads();

    // precompute ecq[n][h] = sum_f c1[f] * q[n,h,f]
    if (t < BROWS * HH) {
        int n = t >> 2, h = t & 3;
        const ull* qp = (const ull*)&sq[n][h * FF];
        const ull* cp = (const ull*)c1s;
        ull s = 0;
#pragma unroll
        for (int i = 0; i < FF / 2; i++) s = fma2(cp[i], qp[i], s);
        ecq_s[n][h] = hsum2(s);
    }

    int em   = t & 31;
    int wrp  = t >> 5;
    int eh   = wrp & 3;        // head
    int half = wrp >> 2;       // 0..1 -> n base = half*4
    int nb   = half * 4;

    // agg mapping: thread = output column c = t, head = c/64
    int ah = t >> 6;

    float dsum[4] = {0.f, 0.f, 0.f, 0.f};
    ull accp[4] = {0ULL, 0ULL, 0ULL, 0ULL};   // n-pairs (01,23,45,67)

    const ulonglong2* qb  = (const ulonglong2*)&sq[nb][eh * FF];  // n stride = 64 ulonglong2
    const ulonglong2* c1p = (const ulonglong2*)c1s;
    const ulonglong2* c2p = (const ulonglong2*)c2s;

    for (int tile = 0; tile < NTILES; tile++) {
        int m0 = mbase + tile * TMm;
        __syncthreads();  // previous agg done before overwriting gl2 / w_t

        // load g_l tile as 16B groups: gl2[h][fp2][m]
        for (int i = t; i < TMm * (CD / 4); i += 256) {
            int m   = i >> 6;        // 0..31
            int cc2 = i & 63;        // global 4-f group (h*16 + fp2)
            ulonglong2 v = *(const ulonglong2*)(g_gl + (size_t)(m0 + m) * CD + 4 * cc2);
            gl2[cc2 >> 4][cc2 & 15][m] = v;
        }
        __syncthreads();

        // ---- e-phase: e[n0+nb .. +3, m0+em, eh] ----
        {
            ull aB0 = 0, aB1 = 0, aB2 = 0, aB3 = 0;
            ull ecg = 0;
            const ulonglong2* gp = &gl2[eh][0][em];
#pragma unroll
            for (int fp2 = 0; fp2 < FF / 4; fp2++) {
                ulonglong2 c1v = c1p[fp2];
                ulonglong2 c2v = c2p[fp2];
                ulonglong2 g   = gp[fp2 * (TMm + 1)];
                ecg = fma2(c1v.x, g.x, ecg);
                ecg = fma2(c1v.y, g.y, ecg);
                ull x0, x1;
                ulonglong2 qv;
#define EABS(N, ACC) \
                qv = qb[(N) * 64 + fp2]; \
                x0 = add2(qv.x, g.x); x1 = add2(qv.y, g.y); \
                ACC = fma2(c2v.x, x0 & ABSM, ACC); \
                ACC = fma2(c2v.y, x1 & ABSM, ACC);
                EABS(0, aB0) EABS(1, aB1) EABS(2, aB2) EABS(3, aB3)
#undef EABS
            }
            float ecgs = hsum2(ecg);

            // mask by adj_mat[m, n] (adj.T in the reference), exponentiate
            const float* arow = adj + (size_t)(m0 + em) * NN + n0 + nb;
            float4 am = *(const float4*)arow;
            float w0 = (am.x != 0.f) ? __expf(hsum2(aB0) + ecgs + ecq_s[nb + 0][eh]) : 0.f;
            float w1 = (am.y != 0.f) ? __expf(hsum2(aB1) + ecgs + ecq_s[nb + 1][eh]) : 0.f;
            float w2 = (am.z != 0.f) ? __expf(hsum2(aB2) + ecgs + ecq_s[nb + 2][eh]) : 0.f;
            float w3 = (am.w != 0.f) ? __expf(hsum2(aB3) + ecgs + ecq_s[nb + 3][eh]) : 0.f;
            dsum[0] += w0; dsum[1] += w1; dsum[2] += w2; dsum[3] += w3;
            *(float4*)&w_t[em][eh * 8 + nb] = make_float4(w0, w1, w2, w3);
        }
        __syncthreads();

        // ---- aggregation: accp[np] += w[n-pair, m, ah] * (gv, gv) ----
        const float* grp = g_gr + (size_t)m0 * CD + t;
#pragma unroll 4
        for (int m = 0; m < TMm; m++) {
            float gv = __ldg(grp + (size_t)m * CD);
            ull gv2 = pack2(gv, gv);
            ulonglong2 wa = *(const ulonglong2*)&w_t[m][ah * 8];
            ulonglong2 wb = *(const ulonglong2*)&w_t[m][ah * 8 + 4];
            accp[0] = fma2(wa.x, gv2, accp[0]);
            accp[1] = fma2(wa.y, gv2, accp[1]);
            accp[2] = fma2(wb.x, gv2, accp[2]);
            accp[3] = fma2(wb.y, gv2, accp[3]);
        }
    }

    // reduce dsum over lanes (lanes = m slices) -> partial denominators
    {
#pragma unroll
        for (int off = 16; off; off >>= 1) {
#pragma unroll
            for (int i = 0; i < 4; i++)
                dsum[i] += __shfl_xor_sync(0xffffffffu, dsum[i], off);
        }
        if (em == 0) {
#pragma unroll
            for (int i = 0; i < 4; i++)
                g_pden[((size_t)sp * NN + n0 + nb + i) * HH + eh] = dsum[i];
        }
    }

    // partial numerators
#pragma unroll
    for (int np = 0; np < 4; np++) {
        float2 v = unpack2(accp[np]);
        g_pacc[((size_t)sp * NN + n0 + 2 * np + 0) * CD + t] = v.x;
        g_pacc[((size_t)sp * NN + n0 + 2 * np + 1) * CD + t] = v.y;
    }
}

// ---------------- combine partials + elu (float4) ----------------
__global__ __launch_bounds__(256)
void combine_kernel(const int* __restrict__ use_elu_p, float* __restrict__ out) {
    int idx = blockIdx.x * 256 + threadIdx.x;        // 0 .. 65535 (float4 slots)
    int n   = idx >> 6;
    int c4  = idx & 63;                              // float4 column
    int h   = c4 >> 4;
    float4 a = make_float4(0.f, 0.f, 0.f, 0.f);
    float  d = 0.f;
#pragma unroll
    for (int sp = 0; sp < NSPLIT; sp++) {
        float4 p = *(const float4*)&g_pacc[((size_t)sp * NN + n) * CD + 4 * c4];
        a.x += p.x; a.y += p.y; a.z += p.z; a.w += p.w;
        d += g_pden[((size_t)sp * NN + n) * HH + h];
    }
    float inv = 1.f / d;
    float4 v = make_float4(a.x * inv, a.y * inv, a.z * inv, a.w * inv);
    if (*use_elu_p) {
        v.x = (v.x > 0.f) ? v.x : expm1f(v.x);
        v.y = (v.y > 0.f) ? v.y : expm1f(v.y);
        v.z = (v.z > 0.f) ? v.z : expm1f(v.z);
        v.w = (v.w > 0.f) ? v.w : expm1f(v.w);
    }
    *(float4*)&out[(size_t)n * CD + 4 * c4] = v;
}

extern "C" void kernel_launch(void* const* d_in, const int* in_sizes, int n_in,
                              void* d_out, int out_size) {
    const float* h    = (const float*)d_in[0];
    const float* nei  = (const float*)d_in[1];
    const float* adj  = (const float*)d_in[2];
    const float* w_l  = (const float*)d_in[3];
    const float* w_r  = (const float*)d_in[4];
    const float* aw   = (const float*)d_in[5];
    const int*   uelu = (const int*)d_in[6];
    float* out = (float*)d_out;

    dim3 ggrid(CD / 64, NN / 32, 2);
    gemm_kernel<<<ggrid, 256>>>(h, w_l, nei, w_r);
    dim3 agrid(NN / BROWS, NSPLIT);
    gat_kernel<<<agrid, 256>>>(adj, aw);
    combine_kernel<<<NN * CD / 4 / 256, 256>>>(uelu, out);
}

// round 7
// speedup vs baseline: 2.2244x; 1.0693x over previous
#include <cuda_runtime.h>

#define NN 1024
#define CD 256
#define HH 4
#define FF 64
#define BROWS 8
#define TMm 32
#define NSPLIT 4
#define MPS (NN / NSPLIT)      // m's per split = 256
#define NTILES (MPS / TMm)     // tiles per split = 8
#define WTS 36                 // w_t row stride (floats)

typedef unsigned long long ull;
#define ABSM 0x7FFFFFFF7FFFFFFFULL

__device__ __forceinline__ ull fma2(ull a, ull b, ull c) {
    ull d;
    asm("fma.rn.f32x2 %0, %1, %2, %3;" : "=l"(d) : "l"(a), "l"(b), "l"(c));
    return d;
}
__device__ __forceinline__ ull add2(ull a, ull b) {
    ull d;
    asm("add.rn.f32x2 %0, %1, %2;" : "=l"(d) : "l"(a), "l"(b));
    return d;
}
__device__ __forceinline__ ull pack2(float lo, float hi) {
    ull d;
    asm("mov.b64 %0, {%1, %2};" : "=l"(d) : "f"(lo), "f"(hi));
    return d;
}
__device__ __forceinline__ float2 unpack2(ull v) {
    float2 r;
    asm("mov.b64 {%0, %1}, %2;" : "=f"(r.x), "=f"(r.y) : "l"(v));
    return r;
}
__device__ __forceinline__ float hsum2(ull v) {
    float2 r = unpack2(v);
    return r.x + r.y;
}

// scratch (device globals: no allocs allowed)
__device__ float g_gl[NN * CD];
__device__ float g_gr[NN * CD];
__device__ float g_ecl[NN * HH];             // 0.6 * sum_f aw[f]*g_l[m,h,f]
__device__ float g_ecr[NN * HH];             // 0.6 * sum_f aw[f]*g_r[n,h,f]
__device__ float g_pacc[NSPLIT * NN * CD];   // partial numerators
__device__ float g_pden[NSPLIT * NN * HH];   // partial denominators

// ------- GEMM: G = X @ W  (1024x256 @ 256x256), 32x64 tiles, 512 thr, db-buffered -------
// Also computes ec[row][head] = 0.6 * sum_f aw[f] * G[row, head*64+f] in the epilogue
// (bn spans exactly one head since CD/64 = HH).
__global__ __launch_bounds__(512)
void gemm_kernel(const float* __restrict__ X0, const float* __restrict__ W0,
                 const float* __restrict__ X1, const float* __restrict__ W1,
                 const float* __restrict__ attn_w) {
    const float* X;
    const float* W;
    float* G;
    float* EC;
    if (blockIdx.z == 0) { X = X0; W = W0; G = g_gl; EC = g_ecl; }
    else                 { X = X1; W = W1; G = g_gr; EC = g_ecr; }

    __shared__ __align__(16) float As[2][16][34];   // [buf][k][row], 136B rows (8B-aligned pairs)
    __shared__ __align__(16) float Bs[2][16][64];   // [buf][k][col]

    int t = threadIdx.x;
    int bm = blockIdx.y * 32;
    int bn = blockIdx.x * 64;
    int head = blockIdx.x;     // bn = head*64
    int tr = t >> 5;           // warp id 0..15 -> rows 2tr, 2tr+1
    int tc = t & 31;           // lane -> cols 2tc, 2tc+1

    // loader indices
    int ar  = t >> 2;            // 0..31 (t<128)
    int ac4 = (t & 3) << 2;
    int bi  = t - 128;           // 0..255 valid for t in [128,384)
    int br  = bi >> 4;           // 0..15
    int bc4 = (bi & 15) << 2;
    bool doA = (t < 128);
    bool doB = (t >= 128 && t < 384);

    ull acc0 = 0, acc1 = 0;

    float4 av, bv;
    if (doA) av = *(const float4*)(X + (size_t)(bm + ar) * CD + ac4);
    if (doB) bv = *(const float4*)(W + (size_t)br * CD + bn + bc4);
    if (doA) {
        As[0][ac4 + 0][ar] = av.x; As[0][ac4 + 1][ar] = av.y;
        As[0][ac4 + 2][ar] = av.z; As[0][ac4 + 3][ar] = av.w;
    }
    if (doB) *(float4*)&Bs[0][br][bc4] = bv;
    __syncthreads();

    for (int kc = 0; kc < 16; kc++) {
        int cur = kc & 1;
        if (kc < 15) {
            if (doA) av = *(const float4*)(X + (size_t)(bm + ar) * CD + (kc + 1) * 16 + ac4);
            if (doB) bv = *(const float4*)(W + (size_t)((kc + 1) * 16 + br) * CD + bn + bc4);
        }
#pragma unroll
        for (int k = 0; k < 16; k++) {
            float2 a = *(const float2*)&As[cur][k][tr * 2];
            ull b = *(const ull*)&Bs[cur][k][tc * 2];
            acc0 = fma2(pack2(a.x, a.x), b, acc0);
            acc1 = fma2(pack2(a.y, a.y), b, acc1);
        }
        if (kc < 15) {
            int nxt = cur ^ 1;
            if (doA) {
                As[nxt][ac4 + 0][ar] = av.x; As[nxt][ac4 + 1][ar] = av.y;
                As[nxt][ac4 + 2][ar] = av.z; As[nxt][ac4 + 3][ar] = av.w;
            }
            if (doB) *(float4*)&Bs[nxt][br][bc4] = bv;
        }
        __syncthreads();
    }

    *(ull*)&G[(size_t)(bm + tr * 2 + 0) * CD + bn + tc * 2] = acc0;
    *(ull*)&G[(size_t)(bm + tr * 2 + 1) * CD + bn + tc * 2] = acc1;

    // ---- ec epilogue: warp-reduce aw-weighted row sums ----
    {
        float2 awv = *(const float2*)(attn_w + 2 * tc);
        float2 r0 = unpack2(acc0), r1 = unpack2(acc1);
        float s0 = awv.x * r0.x + awv.y * r0.y;
        float s1 = awv.x * r1.x + awv.y * r1.y;
#pragma unroll
        for (int off = 16; off; off >>= 1) {
            s0 += __shfl_xor_sync(0xffffffffu, s0, off);
            s1 += __shfl_xor_sync(0xffffffffu, s1, off);
        }
        if (tc == 0) {
            EC[(size_t)(bm + tr * 2 + 0) * HH + head] = 0.6f * s0;
            EC[(size_t)(bm + tr * 2 + 1) * HH + head] = 0.6f * s1;
        }
    }
}

// ---------------- fused GATv2 attention (m-split partials, f32x2) ----------------
// e[n,m,h] = ecr[n,h] + ecl[m,h] + sum_f c2[f]*|q+g|   (c2 = 0.4*aw)
__global__ __launch_bounds__(256, 4)
void gat_kernel(const float* __restrict__ adj, const float* __restrict__ attn_w) {
    __shared__ __align__(16) float sq[BROWS][CD];        // g_r of block rows (queries)
    __shared__ __align__(16) float c2s[FF];              // 0.4*aw
    __shared__ ulonglong2 gl2[HH][FF / 4][TMm + 1];      // g_l tile, 4-f groups [h][fp2][m]
    __shared__ __align__(16) float w_t[TMm][WTS];        // [m][h*8 + n]
    __shared__ float ecr_s[BROWS * HH];                  // [n*4 + h]
    __shared__ float ecl_s[TMm * HH];                    // [m*4 + h]
    __shared__ __align__(16) float adj_s[TMm][8];        // adj tile [m][n]

    int t  = threadIdx.x;
    int n0 = blockIdx.x * BROWS;
    int sp = blockIdx.y;
    int mbase = sp * MPS;

    // load queries (as 16B) + coefficient vector + ecr
    {
        ulonglong2* sq2 = (ulonglong2*)sq;
        for (int i = t; i < BROWS * CD / 4; i += 256) {
            int r = i >> 6, c2 = i & 63;
            sq2[i] = *(const ulonglong2*)(g_gr + (size_t)(n0 + r) * CD + 4 * c2);
        }
    }
    if (t < FF) c2s[t] = 0.4f * attn_w[t];
    if (t >= 64 && t < 64 + BROWS * HH) ecr_s[t - 64] = g_ecr[n0 * HH + (t - 64)];

    int em   = t & 31;
    int wrp  = t >> 5;
    int eh   = wrp & 3;        // head
    int half = wrp >> 2;       // 0..1 -> n base = half*4
    int nb   = half * 4;

    // agg mapping: thread = output column c = t, head = c/64
    int ah = t >> 6;

    float dsum[4] = {0.f, 0.f, 0.f, 0.f};
    ull accp[4] = {0ULL, 0ULL, 0ULL, 0ULL};   // n-pairs (01,23,45,67)

    const ulonglong2* qb  = (const ulonglong2*)&sq[nb][eh * FF];  // n stride = 64 ulonglong2
    const ulonglong2* c2p = (const ulonglong2*)c2s;

    for (int tile = 0; tile < NTILES; tile++) {
        int m0 = mbase + tile * TMm;
        __syncthreads();  // previous agg done before overwriting gl2 / w_t

        // load g_l tile as 16B groups: gl2[h][fp2][m]; plus ecl tile + adj tile
        for (int i = t; i < TMm * (CD / 4); i += 256) {
            int m   = i >> 6;        // 0..31
            int cc2 = i & 63;        // global 4-f group (h*16 + fp2)
            ulonglong2 v = *(const ulonglong2*)(g_gl + (size_t)(m0 + m) * CD + 4 * cc2);
            gl2[cc2 >> 4][cc2 & 15][m] = v;
        }
        if (t < TMm * HH) ecl_s[t] = g_ecl[m0 * HH + t];
        else if (t < TMm * HH + TMm * 2) {
            int i = t - TMm * HH;      // 0..63
            int row = i >> 1, hf = (i & 1) * 4;
            *(float4*)&adj_s[row][hf] =
                *(const float4*)(adj + (size_t)(m0 + row) * NN + n0 + hf);
        }
        __syncthreads();

        // ---- e-phase: e[n0+nb .. +3, m0+em, eh] ----
        {
            ull aB0 = 0, aB1 = 0, aB2 = 0, aB3 = 0;
            const ulonglong2* gp = &gl2[eh][0][em];
#pragma unroll
            for (int fp2 = 0; fp2 < FF / 4; fp2++) {
                ulonglong2 c2v = c2p[fp2];
                ulonglong2 g   = gp[fp2 * (TMm + 1)];
                ull x0, x1;
                ulonglong2 qv;
#define EABS(N, ACC) \
                qv = qb[(N) * 64 + fp2]; \
                x0 = add2(qv.x, g.x); x1 = add2(qv.y, g.y); \
                ACC = fma2(c2v.x, x0 & ABSM, ACC); \
                ACC = fma2(c2v.y, x1 & ABSM, ACC);
                EABS(0, aB0) EABS(1, aB1) EABS(2, aB2) EABS(3, aB3)
#undef EABS
            }
            float base = ecl_s[em * HH + eh];

            float4 am = *(const float4*)&adj_s[em][nb];
            float w0 = (am.x != 0.f) ? __expf(hsum2(aB0) + base + ecr_s[(nb + 0) * HH + eh]) : 0.f;
            float w1 = (am.y != 0.f) ? __expf(hsum2(aB1) + base + ecr_s[(nb + 1) * HH + eh]) : 0.f;
            float w2 = (am.z != 0.f) ? __expf(hsum2(aB2) + base + ecr_s[(nb + 2) * HH + eh]) : 0.f;
            float w3 = (am.w != 0.f) ? __expf(hsum2(aB3) + base + ecr_s[(nb + 3) * HH + eh]) : 0.f;
            dsum[0] += w0; dsum[1] += w1; dsum[2] += w2; dsum[3] += w3;
            *(float4*)&w_t[em][eh * 8 + nb] = make_float4(w0, w1, w2, w3);
        }
        __syncthreads();

        // ---- aggregation: software-pipelined g prefetch (MLP=8) ----
        const float* grp = g_gr + (size_t)m0 * CD + t;
        float gpref[8];
#pragma unroll
        for (int j = 0; j < 8; j++) gpref[j] = __ldg(grp + (size_t)j * CD);
#pragma unroll
        for (int ch = 0; ch < 4; ch++) {
            float gcur[8];
#pragma unroll
            for (int j = 0; j < 8; j++) gcur[j] = gpref[j];
            if (ch < 3) {
#pragma unroll
                for (int j = 0; j < 8; j++)
                    gpref[j] = __ldg(grp + (size_t)((ch + 1) * 8 + j) * CD);
            }
#pragma unroll
            for (int j = 0; j < 8; j++) {
                int m = ch * 8 + j;
                ull gv2 = pack2(gcur[j], gcur[j]);
                ulonglong2 wa = *(const ulonglong2*)&w_t[m][ah * 8];
                ulonglong2 wb = *(const ulonglong2*)&w_t[m][ah * 8 + 4];
                accp[0] = fma2(wa.x, gv2, accp[0]);
                accp[1] = fma2(wa.y, gv2, accp[1]);
                accp[2] = fma2(wb.x, gv2, accp[2]);
                accp[3] = fma2(wb.y, gv2, accp[3]);
            }
        }
    }

    // reduce dsum over lanes (lanes = m slices) -> partial denominators
    {
#pragma unroll
        for (int off = 16; off; off >>= 1) {
#pragma unroll
            for (int i = 0; i < 4; i++)
                dsum[i] += __shfl_xor_sync(0xffffffffu, dsum[i], off);
        }
        if (em == 0) {
#pragma unroll
            for (int i = 0; i < 4; i++)
                g_pden[((size_t)sp * NN + n0 + nb + i) * HH + eh] = dsum[i];
        }
    }

    // partial numerators
#pragma unroll
    for (int np = 0; np < 4; np++) {
        float2 v = unpack2(accp[np]);
        g_pacc[((size_t)sp * NN + n0 + 2 * np + 0) * CD + t] = v.x;
        g_pacc[((size_t)sp * NN + n0 + 2 * np + 1) * CD + t] = v.y;
    }
}

// ---------------- combine partials + elu (float4) ----------------
__global__ __launch_bounds__(256)
void combine_kernel(const int* __restrict__ use_elu_p, float* __restrict__ out) {
    int idx = blockIdx.x * 256 + threadIdx.x;        // 0 .. 65535 (float4 slots)
    int n   = idx >> 6;
    int c4  = idx & 63;                              // float4 column
    int h   = c4 >> 4;
    float4 a = make_float4(0.f, 0.f, 0.f, 0.f);
    float  d = 0.f;
#pragma unroll
    for (int sp = 0; sp < NSPLIT; sp++) {
        float4 p = *(const float4*)&g_pacc[((size_t)sp * NN + n) * CD + 4 * c4];
        a.x += p.x; a.y += p.y; a.z += p.z; a.w += p.w;
        d += g_pden[((size_t)sp * NN + n) * HH + h];
    }
    float inv = 1.f / d;
    float4 v = make_float4(a.x * inv, a.y * inv, a.z * inv, a.w * inv);
    if (*use_elu_p) {
        v.x = (v.x > 0.f) ? v.x : expm1f(v.x);
        v.y = (v.y > 0.f) ? v.y : expm1f(v.y);
        v.z = (v.z > 0.f) ? v.z : expm1f(v.z);
        v.w = (v.w > 0.f) ? v.w : expm1f(v.w);
    }
    *(float4*)&out[(size_t)n * CD + 4 * c4] = v;
}

extern "C" void kernel_launch(void* const* d_in, const int* in_sizes, int n_in,
                              void* d_out, int out_size) {
    const float* h    = (const float*)d_in[0];
    const float* nei  = (const float*)d_in[1];
    const float* adj  = (const float*)d_in[2];
    const float* w_l  = (const float*)d_in[3];
    const float* w_r  = (const float*)d_in[4];
    const float* aw   = (const float*)d_in[5];
    const int*   uelu = (const int*)d_in[6];
    float* out = (float*)d_out;

    dim3 ggrid(CD / 64, NN / 32, 2);
    gemm_kernel<<<ggrid, 512>>>(h, w_l, nei, w_r, aw);
    dim3 agrid(NN / BROWS, NSPLIT);
    gat_kernel<<<agrid, 256>>>(adj, aw);
    combine_kernel<<<NN * CD / 4 / 256, 256>>>(uelu, out);
}